// round 7
// baseline (speedup 1.0000x reference)
#include <cuda_runtime.h>
#include <cuda_fp16.h>

#define BATCH   8192
#define CLASSES 10000
#define C4      2500            // float4 per row
#define TROWS   4               // rows per tile
#define THREADS 512
#define GRID    304             // 2 persistent CTAs/SM
#define NTILES  (BATCH / TROWS) // 2048
#define KCH     10              // half2 columns per thread (512*10 >= 5000)
#define SMEM_BYTES (TROWS * CLASSES * 2)   // 80000 B fp16 exp stage

__device__ float g_part[GRID][CLASSES];   // per-CTA partials (fully overwritten)
__device__ float g_counts[CLASSES];
__device__ float g_sig[CLASSES];          // signed per-class reduced sums

// ---------------------------------------------------------------- zero counts/sig/out
__global__ void k_zero(float* __restrict__ out) {
    int i = blockIdx.x * blockDim.x + threadIdx.x;
    if (i < CLASSES) { g_counts[i] = 0.0f; g_sig[i] = 0.0f; }
    if (i == 0) out[0] = 0.0f;
}

// ---------------------------------------------------------------- persistent main
// Per tile of 4 rows: phase A reads rows once (float4, coalesced), fp32 exp,
// stages fp16 in SMEM, fp32 row sums. Phase B: thread tid accumulates its
// fixed half2 columns {tid + 512k} into 20 registers, reused across ALL its
// tiles. Flush = plain coalesced stores. Zero hot-path atomics. 2 CTAs/SM so
// one CTA's phase B overlaps the sibling's DRAM-bound phase A.
__global__ __launch_bounds__(THREADS, 2) void k_main(const float* __restrict__ x,
                                                     const int* __restrict__ tgt) {
    extern __shared__ __half sm_exp[];      // [TROWS][CLASSES]
    __shared__ float wred[16];
    __shared__ float inv[TROWS];

    const int tid     = threadIdx.x;
    const int r       = tid >> 7;           // 0..3 (128 threads per row)
    const int lane128 = tid & 127;

    // histogram side-job (blocks 0..15, 512 targets each); dtype-robust:
    // detect int64-LE (odd int32 words zero for values < 2^32) vs int32.
    if (blockIdx.x < 16) {
        bool is64 = true;
        #pragma unroll
        for (int j = 1; j < 16; j += 2) is64 = is64 && (tgt[j] == 0);
        int i = blockIdx.x * THREADS + tid;
        int t = is64 ? tgt[2 * i] : tgt[i];
        if (t >= 0 && t < CLASSES) atomicAdd(&g_counts[t], 1.0f);
    }

    float a0[KCH], a1[KCH];
    #pragma unroll
    for (int k = 0; k < KCH; k++) a0[k] = a1[k] = 0.0f;

    const __half2* smh2  = reinterpret_cast<const __half2*>(sm_exp);
    uint2*         smrow = reinterpret_cast<uint2*>(sm_exp + r * CLASSES);

    for (int tile = blockIdx.x; tile < NTILES; tile += GRID) {
        // ---------- phase A: DRAM read + exp + fp16 stage + row sums
        const float4* __restrict__ rp =
            reinterpret_cast<const float4*>(x) +
            ((size_t)tile * TROWS + r) * C4;

        float s = 0.0f;
        #pragma unroll 5
        for (int i = lane128; i < C4; i += 128) {
            float4 v = rp[i];
            float e0 = __expf(v.x), e1 = __expf(v.y);
            float e2 = __expf(v.z), e3 = __expf(v.w);
            s += (e0 + e1) + (e2 + e3);
            __half2 h01 = __floats2half2_rn(e0, e1);
            __half2 h23 = __floats2half2_rn(e2, e3);
            smrow[i] = make_uint2(*reinterpret_cast<unsigned*>(&h01),
                                  *reinterpret_cast<unsigned*>(&h23));
        }

        #pragma unroll
        for (int o = 16; o; o >>= 1) s += __shfl_down_sync(0xffffffffu, s, o);
        if ((tid & 31) == 0) wred[tid >> 5] = s;
        __syncthreads();
        if (tid < TROWS) {
            float t = wred[4 * tid] + wred[4 * tid + 1] +
                      wred[4 * tid + 2] + wred[4 * tid + 3];
            inv[tid] = 1.0f / t;
        }
        __syncthreads();

        const float i0 = inv[0], i1 = inv[1], i2 = inv[2], i3 = inv[3];

        // ---------- phase B: accumulate fixed columns into registers
        #pragma unroll
        for (int k = 0; k < KCH; k++) {
            int j = tid + k * THREADS;
            if (j < CLASSES / 2) {
                float2 f0 = __half22float2(smh2[0 * (CLASSES / 2) + j]);
                float2 f1 = __half22float2(smh2[1 * (CLASSES / 2) + j]);
                float2 f2 = __half22float2(smh2[2 * (CLASSES / 2) + j]);
                float2 f3 = __half22float2(smh2[3 * (CLASSES / 2) + j]);
                a0[k] += f0.x * i0 + f1.x * i1 + f2.x * i2 + f3.x * i3;
                a1[k] += f0.y * i0 + f1.y * i1 + f2.y * i2 + f3.y * i3;
            }
        }
        __syncthreads();   // protect stage/wred/inv before next tile overwrites
    }

    // flush per-CTA partials: coalesced float2 stores
    float2* __restrict__ dst = reinterpret_cast<float2*>(g_part[blockIdx.x]);
    #pragma unroll
    for (int k = 0; k < KCH; k++) {
        int j = tid + k * THREADS;
        if (j < CLASSES / 2) dst[j] = make_float2(a0[k], a1[k]);
    }
}

// ---------------------------------------------------------------- reduce stage 1
// 2-D grid: x tiles classes (10 blocks), y tiles the 304 partials into 4
// chunks of 76. Signed partial per class accumulated via atomicAdd (4 adds
// per address — negligible), counts subtracted once by y==0.
__global__ __launch_bounds__(256) void k_red1() {
    const int p0 = blockIdx.y * (GRID / 4);
    for (int c = blockIdx.x * 256 + threadIdx.x; c < CLASSES; c += gridDim.x * 256) {
        float v = 0.0f;
        #pragma unroll 4
        for (int p = p0; p < p0 + GRID / 4; p++) v += g_part[p][c];
        if (blockIdx.y == 0) v -= g_counts[c];
        atomicAdd(&g_sig[c], v);
    }
}

// ---------------------------------------------------------------- reduce stage 2
__global__ __launch_bounds__(1024) void k_red2(float* __restrict__ out) {
    const float invB = 1.0f / (float)BATCH;
    float s = 0.0f;
    for (int c = threadIdx.x; c < CLASSES; c += 1024)
        s += fabsf(g_sig[c] * invB);
    __shared__ float sm[32];
    #pragma unroll
    for (int o = 16; o; o >>= 1) s += __shfl_down_sync(0xffffffffu, s, o);
    if ((threadIdx.x & 31) == 0) sm[threadIdx.x >> 5] = s;
    __syncthreads();
    if (threadIdx.x < 32) {
        float t = sm[threadIdx.x];
        #pragma unroll
        for (int o = 16; o; o >>= 1) t += __shfl_down_sync(0xffffffffu, t, o);
        if (threadIdx.x == 0) out[0] = t / (float)CLASSES;
    }
}

// ---------------------------------------------------------------- launch
extern "C" void kernel_launch(void* const* d_in, const int* in_sizes, int n_in,
                              void* d_out, int out_size) {
    const float* x   = (const float*)d_in[0];   // [8192, 10000] fp32
    const int*   tgt = (const int*)d_in[1];     // [8192] int32 or int64 (detected)
    float*       out = (float*)d_out;

    cudaFuncSetAttribute(k_main, cudaFuncAttributeMaxDynamicSharedMemorySize,
                         SMEM_BYTES);

    k_zero<<<(CLASSES + 255) / 256, 256>>>(out);
    k_main<<<GRID, THREADS, SMEM_BYTES>>>(x, tgt);
    k_red1<<<dim3(10, 4), 256>>>();
    k_red2<<<1, 1024>>>(out);
}

// round 8
// speedup vs baseline: 1.1158x; 1.1158x over previous
#include <cuda_runtime.h>
#include <cuda_fp16.h>

#define BATCH   8192
#define CLASSES 10000
#define C4      2500            // float4 per row
#define TROWS   4               // rows per tile
#define THREADS 512
#define MAXGRID 320             // upper bound for 2 CTAs/SM on <=160 SMs
#define NTILES  (BATCH / TROWS) // 2048
#define KCH     10              // half2 columns per thread (512*10 >= 5000)
#define SMEM_BYTES (TROWS * CLASSES * 2)   // 80000 B fp16 exp stage

__device__ float g_part[MAXGRID][CLASSES];   // per-CTA partials (overwritten)

// ---------------------------------------------------------------- out = 0
__global__ void k_zero(float* __restrict__ out) {
    if (threadIdx.x == 0) out[0] = 0.0f;
}

// ---------------------------------------------------------------- persistent main
// grid = 2 * SM count (queried at launch; no wave tail). Per tile of 4 rows:
// phase A reads rows once (float4, coalesced), fp32 exp, stages fp16 in SMEM,
// fp32 row sums. Phase B: thread tid accumulates its fixed half2 columns
// {tid + 512k, k<10} into 20 registers, reused across ALL its tiles.
// Flush = plain coalesced stores. Zero hot-path atomics, no spills
// (phase A unroll kept at 3 so live regs stay under the 64-reg cap).
__global__ __launch_bounds__(THREADS, 2) void k_main(const float* __restrict__ x) {
    extern __shared__ __half sm_exp[];      // [TROWS][CLASSES]
    __shared__ float wred[16];
    __shared__ float inv[TROWS];

    const int tid     = threadIdx.x;
    const int r       = tid >> 7;           // 0..3 (128 threads per row)
    const int lane128 = tid & 127;

    float a0[KCH], a1[KCH];
    #pragma unroll
    for (int k = 0; k < KCH; k++) a0[k] = a1[k] = 0.0f;

    const __half2* smh2  = reinterpret_cast<const __half2*>(sm_exp);
    uint2*         smrow = reinterpret_cast<uint2*>(sm_exp + r * CLASSES);

    for (int tile = blockIdx.x; tile < NTILES; tile += gridDim.x) {
        // ---------- phase A: DRAM read + exp + fp16 stage + row sums
        const float4* __restrict__ rp =
            reinterpret_cast<const float4*>(x) +
            ((size_t)tile * TROWS + r) * C4;

        float s = 0.0f;
        #pragma unroll 3
        for (int i = lane128; i < C4; i += 128) {
            float4 v = rp[i];
            float e0 = __expf(v.x), e1 = __expf(v.y);
            float e2 = __expf(v.z), e3 = __expf(v.w);
            s += (e0 + e1) + (e2 + e3);
            __half2 h01 = __floats2half2_rn(e0, e1);
            __half2 h23 = __floats2half2_rn(e2, e3);
            smrow[i] = make_uint2(*reinterpret_cast<unsigned*>(&h01),
                                  *reinterpret_cast<unsigned*>(&h23));
        }

        #pragma unroll
        for (int o = 16; o; o >>= 1) s += __shfl_down_sync(0xffffffffu, s, o);
        if ((tid & 31) == 0) wred[tid >> 5] = s;
        __syncthreads();
        if (tid < TROWS) {
            float t = wred[4 * tid] + wred[4 * tid + 1] +
                      wred[4 * tid + 2] + wred[4 * tid + 3];
            inv[tid] = 1.0f / t;
        }
        __syncthreads();

        const float i0 = inv[0], i1 = inv[1], i2 = inv[2], i3 = inv[3];

        // ---------- phase B: accumulate fixed columns into registers
        #pragma unroll
        for (int k = 0; k < KCH; k++) {
            int j = tid + k * THREADS;
            if (j < CLASSES / 2) {
                float2 f0 = __half22float2(smh2[0 * (CLASSES / 2) + j]);
                float2 f1 = __half22float2(smh2[1 * (CLASSES / 2) + j]);
                float2 f2 = __half22float2(smh2[2 * (CLASSES / 2) + j]);
                float2 f3 = __half22float2(smh2[3 * (CLASSES / 2) + j]);
                a0[k] += f0.x * i0 + f1.x * i1 + f2.x * i2 + f3.x * i3;
                a1[k] += f0.y * i0 + f1.y * i1 + f2.y * i2 + f3.y * i3;
            }
        }
        __syncthreads();   // protect stage/wred/inv before next tile overwrites
    }

    // flush per-CTA partials: coalesced float2 stores
    float2* __restrict__ dst = reinterpret_cast<float2*>(g_part[blockIdx.x]);
    #pragma unroll
    for (int k = 0; k < KCH; k++) {
        int j = tid + k * THREADS;
        if (j < CLASSES / 2) dst[j] = make_float2(a0[k], a1[k]);
    }
}

// ---------------------------------------------------------------- fused epilogue
// 100 blocks, each owning 100 classes. Builds the label histogram for its
// class range in SMEM (tgt is tiny and L2-hot), sums the per-CTA partials
// (coalesced across the 100-class span), takes |conf - count|/B, reduces,
// one atomicAdd to out per block.
__global__ __launch_bounds__(256) void k_fin(const int* __restrict__ tgt,
                                             float* __restrict__ out, int nb) {
    __shared__ int   hist[100];
    __shared__ float sm[8];
    const int tid = threadIdx.x;
    const int c0  = blockIdx.x * 100;

    if (tid < 100) hist[tid] = 0;
    __syncthreads();

    // dtype-robust target read: detect int64-LE (odd int32 words zero for
    // values < 2^32) vs int32.
    bool is64 = true;
    #pragma unroll
    for (int j = 1; j < 16; j += 2) is64 = is64 && (tgt[j] == 0);
    for (int i = tid; i < BATCH; i += 256) {
        int t = is64 ? tgt[2 * i] : tgt[i];
        if (t >= c0 && t < c0 + 100) atomicAdd(&hist[t - c0], 1);
    }
    __syncthreads();

    float s = 0.0f;
    if (tid < 100) {
        const int c = c0 + tid;
        float v = 0.0f;
        #pragma unroll 4
        for (int p = 0; p < nb; p++) v += g_part[p][c];
        s = fabsf(v - (float)hist[tid]) * (1.0f / (float)BATCH);
    }

    #pragma unroll
    for (int o = 16; o; o >>= 1) s += __shfl_down_sync(0xffffffffu, s, o);
    if ((tid & 31) == 0) sm[tid >> 5] = s;
    __syncthreads();
    if (tid < 8) {
        float t = sm[tid];
        t += __shfl_down_sync(0xffu, t, 4);
        t += __shfl_down_sync(0xffu, t, 2);
        t += __shfl_down_sync(0xffu, t, 1);
        if (tid == 0) atomicAdd(out, t / (float)CLASSES);
    }
}

// ---------------------------------------------------------------- launch
extern "C" void kernel_launch(void* const* d_in, const int* in_sizes, int n_in,
                              void* d_out, int out_size) {
    const float* x   = (const float*)d_in[0];   // [8192, 10000] fp32
    const int*   tgt = (const int*)d_in[1];     // [8192] int32 or int64 (detected)
    float*       out = (float*)d_out;

    int sms = 0;
    cudaDeviceGetAttribute(&sms, cudaDevAttrMultiProcessorCount, 0);
    int grid = 2 * sms;                      // exact 2 CTAs/SM, no wave tail
    if (grid < 2)        grid = 2;
    if (grid > MAXGRID)  grid = MAXGRID;

    cudaFuncSetAttribute(k_main, cudaFuncAttributeMaxDynamicSharedMemorySize,
                         SMEM_BYTES);

    k_zero<<<1, 32>>>(out);
    k_main<<<grid, THREADS, SMEM_BYTES>>>(x);
    k_fin<<<100, 256>>>(tgt, out, grid);
}

// round 9
// speedup vs baseline: 1.3427x; 1.2034x over previous
#include <cuda_runtime.h>
#include <cuda_fp16.h>

#define BATCH   8192
#define CLASSES 10000
#define C4      2500            // float4 per row
#define ROWS    8               // rows per block
#define THREADS 1024
#define NREP    8               // replica accumulator arrays
#define SMEM_BYTES (ROWS * CLASSES * 2)   // 160000 B fp16 exp stage

__device__ float g_part[NREP][CLASSES];

// ---------------------------------------------------------------- zero replicas + out
__global__ void k_zero(float* __restrict__ out) {
    int i = blockIdx.x * blockDim.x + threadIdx.x;
    if (i < CLASSES) {
        #pragma unroll
        for (int r = 0; r < NREP; r++) g_part[r][i] = 0.0f;
    }
    if (i == 0) out[0] = 0.0f;
}

// ---------------------------------------------------------------- main (== R3, proven 78.6us config)
// Block b owns rows [8b, 8b+8). Phase A: read rows once (float4, coalesced),
// fp32 exp, stage fp16 in SMEM, fp32 row sums. Phase B: sweep classes from
// SMEM, one atomicAdd per class per block into one of 8 replica arrays.
__global__ __launch_bounds__(THREADS, 1) void k_main(const float* __restrict__ x) {
    extern __shared__ __half sm_exp[];      // [ROWS][CLASSES]
    __shared__ float wsum[32];
    __shared__ float inv[ROWS];

    const int tid     = threadIdx.x;
    const int r       = tid >> 7;           // 0..7  (128 threads per row)
    const int lane128 = tid & 127;
    const size_t row  = (size_t)blockIdx.x * ROWS + r;

    const float4* __restrict__ rowp =
        reinterpret_cast<const float4*>(x + row * CLASSES);
    uint2* smrow8 = reinterpret_cast<uint2*>(sm_exp + r * CLASSES);  // STS.64

    float s = 0.0f;
    #pragma unroll 4
    for (int i = lane128; i < C4; i += 128) {
        float4 v = rowp[i];
        float e0 = __expf(v.x), e1 = __expf(v.y);
        float e2 = __expf(v.z), e3 = __expf(v.w);
        s += (e0 + e1) + (e2 + e3);
        __half2 h01 = __floats2half2_rn(e0, e1);
        __half2 h23 = __floats2half2_rn(e2, e3);
        smrow8[i] = make_uint2(*reinterpret_cast<unsigned*>(&h01),
                               *reinterpret_cast<unsigned*>(&h23));
    }

    // reduce 128 threads per row: warp shfl -> 4 warp sums -> combine
    #pragma unroll
    for (int o = 16; o; o >>= 1) s += __shfl_down_sync(0xffffffffu, s, o);
    if ((tid & 31) == 0) wsum[tid >> 5] = s;
    __syncthreads();
    if (tid < ROWS) {
        float t = wsum[4 * tid] + wsum[4 * tid + 1] +
                  wsum[4 * tid + 2] + wsum[4 * tid + 3];
        inv[tid] = 1.0f / t;
    }
    __syncthreads();

    // Phase B: per-class accumulation from SMEM (half2 = 2 classes at a time)
    float iv[ROWS];
    #pragma unroll
    for (int rr = 0; rr < ROWS; rr++) iv[rr] = inv[rr];

    float* __restrict__ dst = g_part[blockIdx.x & (NREP - 1)];
    const __half2* smh2 = reinterpret_cast<const __half2*>(sm_exp);

    for (int j = tid; j < CLASSES / 2; j += THREADS) {
        float a0 = 0.0f, a1 = 0.0f;
        #pragma unroll
        for (int rr = 0; rr < ROWS; rr++) {
            float2 f = __half22float2(smh2[rr * (CLASSES / 2) + j]);
            a0 += f.x * iv[rr];
            a1 += f.y * iv[rr];
        }
        atomicAdd(&dst[2 * j],     a0);
        atomicAdd(&dst[2 * j + 1], a1);
    }
}

// ---------------------------------------------------------------- fused epilogue
// 100 blocks, each owning 100 classes. Builds the label histogram for its
// class range in SMEM (tgt is tiny and L2-hot), sums the 8 replica partials,
// takes |conf - count|/B, block-reduces, one atomicAdd to out per block.
__global__ __launch_bounds__(256) void k_fin(const int* __restrict__ tgt,
                                             float* __restrict__ out) {
    __shared__ int   hist[100];
    __shared__ float sm[8];
    const int tid = threadIdx.x;
    const int c0  = blockIdx.x * 100;

    if (tid < 100) hist[tid] = 0;
    __syncthreads();

    // dtype-robust target read: detect int64-LE (odd int32 words zero for
    // values < 2^32) vs int32.
    bool is64 = true;
    #pragma unroll
    for (int j = 1; j < 16; j += 2) is64 = is64 && (tgt[j] == 0);
    for (int i = tid; i < BATCH; i += 256) {
        int t = is64 ? tgt[2 * i] : tgt[i];
        if (t >= c0 && t < c0 + 100) atomicAdd(&hist[t - c0], 1);
    }
    __syncthreads();

    float s = 0.0f;
    if (tid < 100) {
        const int c = c0 + tid;
        float v = 0.0f;
        #pragma unroll
        for (int p = 0; p < NREP; p++) v += g_part[p][c];
        s = fabsf(v - (float)hist[tid]) * (1.0f / (float)BATCH);
    }

    #pragma unroll
    for (int o = 16; o; o >>= 1) s += __shfl_down_sync(0xffffffffu, s, o);
    if ((tid & 31) == 0) sm[tid >> 5] = s;
    __syncthreads();
    if (tid < 8) {
        float t = sm[tid];
        t += __shfl_down_sync(0xffu, t, 4);
        t += __shfl_down_sync(0xffu, t, 2);
        t += __shfl_down_sync(0xffu, t, 1);
        if (tid == 0) atomicAdd(out, t / (float)CLASSES);
    }
}

// ---------------------------------------------------------------- launch
extern "C" void kernel_launch(void* const* d_in, const int* in_sizes, int n_in,
                              void* d_out, int out_size) {
    const float* x   = (const float*)d_in[0];   // [8192, 10000] fp32
    const int*   tgt = (const int*)d_in[1];     // [8192] int32 or int64 (detected)
    float*       out = (float*)d_out;

    cudaFuncSetAttribute(k_main, cudaFuncAttributeMaxDynamicSharedMemorySize,
                         SMEM_BYTES);

    k_zero<<<(CLASSES + 255) / 256, 256>>>(out);
    k_main<<<BATCH / ROWS, THREADS, SMEM_BYTES>>>(x);   // 1024 blocks
    k_fin<<<100, 256>>>(tgt, out);
}

// round 10
// speedup vs baseline: 1.3788x; 1.0268x over previous
#include <cuda_runtime.h>
#include <cuda_fp16.h>

#define BATCH   8192
#define CLASSES 10000
#define C4      2500            // float4 (= 4-class group) count per row
#define ROWS    4               // rows per block (80 KB stage -> 2 CTAs/SM)
#define THREADS 512
#define NBLOCKS (BATCH / ROWS)  // 2048
#define NREP    8               // replica accumulator arrays
#define SMEM_BYTES (ROWS * CLASSES * 2)   // 80000 B fp16 exp stage

__device__ float g_part[NREP][CLASSES];

// ---------------------------------------------------------------- zero replicas + out
__global__ void k_zero(float* __restrict__ out) {
    int i = blockIdx.x * blockDim.x + threadIdx.x;
    if (i < CLASSES) {
        #pragma unroll
        for (int r = 0; r < NREP; r++) g_part[r][i] = 0.0f;
    }
    if (i == 0) out[0] = 0.0f;
}

// ---------------------------------------------------------------- main
// Block b owns rows [4b, 4b+4). Phase A: read rows once (float4, coalesced),
// fp32 exp, stage fp16 in SMEM, fp32 row sums. Phase B: per 4-class group,
// sum over the 4 rows and issue ONE red.global.add.v4.f32 into a replica
// array (5.1M vector-REDs total, ~1/3 of the measured L2 atomic ceiling).
// 2 CTAs/SM: one CTA's phase B overlaps the sibling's DRAM-bound phase A.
__global__ __launch_bounds__(THREADS, 2) void k_main(const float* __restrict__ x) {
    extern __shared__ __half sm_exp[];      // [ROWS][CLASSES]
    __shared__ float wred[16];
    __shared__ float inv[ROWS];

    const int tid     = threadIdx.x;
    const int r       = tid >> 7;           // 0..3 (128 threads per row)
    const int lane128 = tid & 127;

    // ---------- phase A
    const float4* __restrict__ rowp =
        reinterpret_cast<const float4*>(x) +
        ((size_t)blockIdx.x * ROWS + r) * C4;
    uint2* smrow8 = reinterpret_cast<uint2*>(sm_exp + r * CLASSES);  // STS.64

    float s = 0.0f;
    #pragma unroll 4
    for (int i = lane128; i < C4; i += 128) {
        float4 v = rowp[i];
        float e0 = __expf(v.x), e1 = __expf(v.y);
        float e2 = __expf(v.z), e3 = __expf(v.w);
        s += (e0 + e1) + (e2 + e3);
        __half2 h01 = __floats2half2_rn(e0, e1);
        __half2 h23 = __floats2half2_rn(e2, e3);
        smrow8[i] = make_uint2(*reinterpret_cast<unsigned*>(&h01),
                               *reinterpret_cast<unsigned*>(&h23));
    }

    // row sums: warp shfl -> 16 warp partials -> row r owns warps 4r..4r+3
    #pragma unroll
    for (int o = 16; o; o >>= 1) s += __shfl_down_sync(0xffffffffu, s, o);
    if ((tid & 31) == 0) wred[tid >> 5] = s;
    __syncthreads();
    if (tid < ROWS) {
        float t = wred[4 * tid] + wred[4 * tid + 1] +
                  wred[4 * tid + 2] + wred[4 * tid + 3];
        inv[tid] = 1.0f / t;
    }
    __syncthreads();

    const float i0 = inv[0], i1 = inv[1], i2 = inv[2], i3 = inv[3];

    // ---------- phase B: one v4 RED per 4-class group
    float* __restrict__ rep = g_part[blockIdx.x & (NREP - 1)];

    #pragma unroll
    for (int k = 0; k < 5; k++) {
        int j = tid + k * THREADS;           // 4-class group index
        if (j < C4) {
            float a0 = 0.f, a1 = 0.f, a2 = 0.f, a3 = 0.f;
            #pragma unroll
            for (int rr = 0; rr < ROWS; rr++) {
                uint2 u = reinterpret_cast<const uint2*>(sm_exp + rr * CLASSES)[j];
                float2 f01 = __half22float2(*reinterpret_cast<__half2*>(&u.x));
                float2 f23 = __half22float2(*reinterpret_cast<__half2*>(&u.y));
                float iv = (rr == 0) ? i0 : (rr == 1) ? i1 : (rr == 2) ? i2 : i3;
                a0 += f01.x * iv; a1 += f01.y * iv;
                a2 += f23.x * iv; a3 += f23.y * iv;
            }
            float* p = rep + 4 * j;          // 16B-aligned
            asm volatile("red.global.add.v4.f32 [%0], {%1, %2, %3, %4};"
                         :: "l"(p), "f"(a0), "f"(a1), "f"(a2), "f"(a3)
                         : "memory");
        }
    }
}

// ---------------------------------------------------------------- fused epilogue
// 100 blocks x 100 classes: SMEM label histogram from the L2-hot target
// array, sum the 8 replicas, |conf - count|/B, block-reduce, one atomicAdd.
__global__ __launch_bounds__(256) void k_fin(const int* __restrict__ tgt,
                                             float* __restrict__ out) {
    __shared__ int   hist[100];
    __shared__ float sm[8];
    const int tid = threadIdx.x;
    const int c0  = blockIdx.x * 100;

    if (tid < 100) hist[tid] = 0;
    __syncthreads();

    // dtype-robust target read: detect int64-LE (odd int32 words zero for
    // values < 2^32) vs int32.
    bool is64 = true;
    #pragma unroll
    for (int j = 1; j < 16; j += 2) is64 = is64 && (tgt[j] == 0);
    for (int i = tid; i < BATCH; i += 256) {
        int t = is64 ? tgt[2 * i] : tgt[i];
        if (t >= c0 && t < c0 + 100) atomicAdd(&hist[t - c0], 1);
    }
    __syncthreads();

    float s = 0.0f;
    if (tid < 100) {
        const int c = c0 + tid;
        float v = 0.0f;
        #pragma unroll
        for (int p = 0; p < NREP; p++) v += g_part[p][c];
        s = fabsf(v - (float)hist[tid]) * (1.0f / (float)BATCH);
    }

    #pragma unroll
    for (int o = 16; o; o >>= 1) s += __shfl_down_sync(0xffffffffu, s, o);
    if ((tid & 31) == 0) sm[tid >> 5] = s;
    __syncthreads();
    if (tid < 8) {
        float t = sm[tid];
        t += __shfl_down_sync(0xffu, t, 4);
        t += __shfl_down_sync(0xffu, t, 2);
        t += __shfl_down_sync(0xffu, t, 1);
        if (tid == 0) atomicAdd(out, t / (float)CLASSES);
    }
}

// ---------------------------------------------------------------- launch
extern "C" void kernel_launch(void* const* d_in, const int* in_sizes, int n_in,
                              void* d_out, int out_size) {
    const float* x   = (const float*)d_in[0];   // [8192, 10000] fp32
    const int*   tgt = (const int*)d_in[1];     // [8192] int32 or int64 (detected)
    float*       out = (float*)d_out;

    cudaFuncSetAttribute(k_main, cudaFuncAttributeMaxDynamicSharedMemorySize,
                         SMEM_BYTES);

    k_zero<<<(CLASSES + 255) / 256, 256>>>(out);
    k_main<<<NBLOCKS, THREADS, SMEM_BYTES>>>(x);   // 2048 blocks, 2/SM
    k_fin<<<100, 256>>>(tgt, out);
}

// round 11
// speedup vs baseline: 1.4948x; 1.0841x over previous
#include <cuda_runtime.h>
#include <cuda_fp16.h>
#include <cstdint>

#define BATCH   8192
#define CLASSES 10000
#define C4      2500                    // float4 per row
#define TROWS   2                       // rows per tile
#define NTILES  (BATCH / TROWS)         // 4096
#define THREADS 1024
#define MAXGRID 160
#define TILE_BYTES (TROWS * CLASSES * 4)     // 80000 raw fp32 per tile
#define STAGE_OFF  (2 * TILE_BYTES)          // fp16 stage after the 2-buffer ring
#define SMEM_DYN   (2 * TILE_BYTES + TROWS * CLASSES * 2)   // 200000 B

__device__ float g_part[MAXGRID][CLASSES];   // per-CTA partials (overwritten)

// ---------------------------------------------------------------- helpers
__device__ __forceinline__ uint32_t s2u(const void* p) {
    uint32_t a;
    asm("{ .reg .u64 t; cvta.to.shared.u64 t, %1; cvt.u32.u64 %0, t; }"
        : "=r"(a) : "l"(p));
    return a;
}

__device__ __forceinline__ void mbar_init(uint32_t mb, uint32_t cnt) {
    asm volatile("mbarrier.init.shared.b64 [%0], %1;" :: "r"(mb), "r"(cnt) : "memory");
}

__device__ __forceinline__ void mbar_wait(uint32_t mb, uint32_t parity) {
    asm volatile(
        "{\n\t"
        ".reg .pred P;\n\t"
        "WL_%=: mbarrier.try_wait.parity.acquire.cta.shared::cta.b64 P, [%0], %1, 0x989680;\n\t"
        "@P bra.uni WD_%=;\n\t"
        "bra.uni WL_%=;\n\t"
        "WD_%=:\n\t"
        "}" :: "r"(mb), "r"(parity) : "memory");
}

// one elected thread: expect_tx + 4 bulk-async 20000B copies (one tile)
__device__ __forceinline__ void issue_tile(const float* __restrict__ x,
                                           char* dyn, uint32_t mb,
                                           int buf, long long tile) {
    asm volatile("mbarrier.arrive.expect_tx.shared.b64 _, [%0], %1;"
                 :: "r"(mb), "r"((uint32_t)TILE_BYTES) : "memory");
    const char* src = (const char*)x + (size_t)tile * TILE_BYTES;
    uint32_t dst = s2u(dyn + buf * TILE_BYTES);
    #pragma unroll
    for (int c = 0; c < 4; c++) {
        asm volatile(
            "cp.async.bulk.shared::cta.global.mbarrier::complete_tx::bytes "
            "[%0], [%1], %2, [%3];"
            :: "r"(dst + c * 20000), "l"(src + (size_t)c * 20000),
               "r"(20000u), "r"(mb) : "memory");
    }
}

// ---------------------------------------------------------------- persistent main
// 1 CTA/SM, 1024 threads. Double-buffered cp.async.bulk keeps DRAM fed by
// construction while threads do exp / SMEM / FMA work. Per-class accumulation
// lives in 12 registers per thread (fixed class<->thread map across tiles);
// flush = 3 coalesced STG.128 per thread into g_part[blockIdx.x].
__global__ __launch_bounds__(THREADS, 1) void k_main(const float* __restrict__ x,
                                                     float* __restrict__ out,
                                                     int grid) {
    extern __shared__ char dyn[];
    __shared__ float    wred[32];
    __shared__ float    inv[TROWS];
    __shared__ uint64_t mbar[2];

    const int tid = threadIdx.x;
    const int bid = blockIdx.x;
    if (bid == 0 && tid == 0) out[0] = 0.0f;   // out is poisoned; k_fin atomicAdds

    const uint32_t mb0 = s2u(&mbar[0]);
    const uint32_t mb1 = s2u(&mbar[1]);
    if (tid == 0) { mbar_init(mb0, 1); mbar_init(mb1, 1); }
    __syncthreads();

    const int n = (NTILES - 1 - bid) / grid + 1;   // tiles owned by this CTA
    if (tid == 0) {
        issue_tile(x, dyn, mb0, 0, bid);
        if (n > 1) issue_tile(x, dyn, mb1, 1, bid + (long long)grid);
    }

    float acc[3][4];
    #pragma unroll
    for (int k = 0; k < 3; k++)
        acc[k][0] = acc[k][1] = acc[k][2] = acc[k][3] = 0.0f;

    const int r = tid >> 9;          // 0..1 (512 threads per row)
    const int l = tid & 511;
    int ph0 = 0, ph1 = 0;

    for (int i = 0; i < n; i++) {
        const int buf = i & 1;
        const uint32_t mb = buf ? mb1 : mb0;
        mbar_wait(mb, buf ? ph1 : ph0);
        if (buf) ph1 ^= 1; else ph0 ^= 1;

        // ---- rowsum pass: raw fp32 from SMEM -> exp -> fp16 stage + sum
        const float4* raw4 = reinterpret_cast<const float4*>(dyn + buf * TILE_BYTES) + r * C4;
        uint2*        st   = reinterpret_cast<uint2*>(dyn + STAGE_OFF) + r * C4;

        float s = 0.0f;
        #pragma unroll
        for (int k = 0; k < 5; k++) {
            int j = l + 512 * k;
            if (j < C4) {
                float4 v = raw4[j];
                float e0 = __expf(v.x), e1 = __expf(v.y);
                float e2 = __expf(v.z), e3 = __expf(v.w);
                s += (e0 + e1) + (e2 + e3);
                __half2 h01 = __floats2half2_rn(e0, e1);
                __half2 h23 = __floats2half2_rn(e2, e3);
                st[j] = make_uint2(*reinterpret_cast<unsigned*>(&h01),
                                   *reinterpret_cast<unsigned*>(&h23));
            }
        }
        #pragma unroll
        for (int o = 16; o; o >>= 1) s += __shfl_down_sync(0xffffffffu, s, o);
        if ((tid & 31) == 0) wred[tid >> 5] = s;
        __syncthreads();                       // raw reads + wred/stage writes done

        // re-arm this buffer for tile i+2 while everyone else proceeds
        if (tid == 0 && i + 2 < n)
            issue_tile(x, dyn, mb, buf, bid + (long long)(i + 2) * grid);

        if (tid < TROWS) {
            float t = 0.0f;
            #pragma unroll
            for (int w = 0; w < 16; w++) t += wred[tid * 16 + w];
            inv[tid] = 1.0f / t;
        }
        __syncthreads();
        const float i0 = inv[0], i1 = inv[1];

        // ---- phase B: accumulate fixed classes into registers
        const uint2* st2 = reinterpret_cast<const uint2*>(dyn + STAGE_OFF);
        #pragma unroll
        for (int k = 0; k < 3; k++) {
            int j = tid + 1024 * k;
            if (j < C4) {
                uint2 u0 = st2[j], u1 = st2[C4 + j];
                float2 a = __half22float2(*reinterpret_cast<__half2*>(&u0.x));
                float2 b = __half22float2(*reinterpret_cast<__half2*>(&u0.y));
                float2 c = __half22float2(*reinterpret_cast<__half2*>(&u1.x));
                float2 d = __half22float2(*reinterpret_cast<__half2*>(&u1.y));
                acc[k][0] += a.x * i0 + c.x * i1;
                acc[k][1] += a.y * i0 + c.y * i1;
                acc[k][2] += b.x * i0 + d.x * i1;
                acc[k][3] += b.y * i0 + d.y * i1;
            }
        }
        __syncthreads();   // stage + wred reuse protection for next tile
    }

    // flush per-CTA partials (no atomics)
    float4* dst = reinterpret_cast<float4*>(g_part[bid]);
    #pragma unroll
    for (int k = 0; k < 3; k++) {
        int j = tid + 1024 * k;
        if (j < C4) dst[j] = make_float4(acc[k][0], acc[k][1], acc[k][2], acc[k][3]);
    }
}

// ---------------------------------------------------------------- fused epilogue
// 100 blocks x 100 classes: SMEM label histogram from the L2-hot target array,
// sum the nb per-CTA partials (L2-hot, 6MB), |conf - count|/B, block-reduce,
// one atomicAdd per block.
__global__ __launch_bounds__(256) void k_fin(const int* __restrict__ tgt,
                                             float* __restrict__ out, int nb) {
    __shared__ int   hist[100];
    __shared__ float sm[8];
    const int tid = threadIdx.x;
    const int c0  = blockIdx.x * 100;

    if (tid < 100) hist[tid] = 0;
    __syncthreads();

    // dtype-robust target read: detect int64-LE (odd int32 words zero for
    // values < 2^32) vs int32.
    bool is64 = true;
    #pragma unroll
    for (int j = 1; j < 16; j += 2) is64 = is64 && (tgt[j] == 0);
    for (int i = tid; i < BATCH; i += 256) {
        int t = is64 ? tgt[2 * i] : tgt[i];
        if (t >= c0 && t < c0 + 100) atomicAdd(&hist[t - c0], 1);
    }
    __syncthreads();

    float s = 0.0f;
    if (tid < 100) {
        const int c = c0 + tid;
        float v = 0.0f;
        #pragma unroll 4
        for (int p = 0; p < nb; p++) v += g_part[p][c];
        s = fabsf(v - (float)hist[tid]) * (1.0f / (float)BATCH);
    }

    #pragma unroll
    for (int o = 16; o; o >>= 1) s += __shfl_down_sync(0xffffffffu, s, o);
    if ((tid & 31) == 0) sm[tid >> 5] = s;
    __syncthreads();
    if (tid < 8) {
        float t = sm[tid];
        t += __shfl_down_sync(0xffu, t, 4);
        t += __shfl_down_sync(0xffu, t, 2);
        t += __shfl_down_sync(0xffu, t, 1);
        if (tid == 0) atomicAdd(out, t / (float)CLASSES);
    }
}

// ---------------------------------------------------------------- launch
extern "C" void kernel_launch(void* const* d_in, const int* in_sizes, int n_in,
                              void* d_out, int out_size) {
    const float* x   = (const float*)d_in[0];   // [8192, 10000] fp32
    const int*   tgt = (const int*)d_in[1];     // [8192] int32 or int64 (detected)
    float*       out = (float*)d_out;

    int sms = 0;
    cudaDeviceGetAttribute(&sms, cudaDevAttrMultiProcessorCount, 0);
    int grid = sms;                              // 1 persistent CTA per SM
    if (grid < 1)       grid = 1;
    if (grid > MAXGRID) grid = MAXGRID;

    cudaFuncSetAttribute(k_main, cudaFuncAttributeMaxDynamicSharedMemorySize,
                         SMEM_DYN);

    k_main<<<grid, THREADS, SMEM_DYN>>>(x, out, grid);
    k_fin<<<100, 256>>>(tgt, out, grid);
}

// round 12
// speedup vs baseline: 1.7682x; 1.1829x over previous
#include <cuda_runtime.h>
#include <cuda_fp16.h>
#include <cstdint>

#define BATCH   8192
#define CLASSES 10000
#define C4      2500                    // float4 per row
#define TROWS   2                       // rows per tile
#define NTILES  (BATCH / TROWS)         // 4096
#define THREADS 1024
#define MAXGRID 160
#define NREP    8
#define TILE_BYTES (TROWS * CLASSES * 4)     // 80000 raw fp32 per tile
#define STAGE_OFF  (2 * TILE_BYTES)          // fp16 stage after the 2-buffer ring
#define SMEM_DYN   (2 * TILE_BYTES + TROWS * CLASSES * 2)   // 200000 B

// zero-initialized at module load; k_fin re-zeroes its slice after each use,
// so the invariant "g_rep == 0 at kernel_launch entry" holds on every call.
__device__ float g_rep[NREP][CLASSES];

// ---------------------------------------------------------------- helpers
__device__ __forceinline__ uint32_t s2u(const void* p) {
    uint32_t a;
    asm("{ .reg .u64 t; cvta.to.shared.u64 t, %1; cvt.u32.u64 %0, t; }"
        : "=r"(a) : "l"(p));
    return a;
}

__device__ __forceinline__ void mbar_init(uint32_t mb, uint32_t cnt) {
    asm volatile("mbarrier.init.shared.b64 [%0], %1;" :: "r"(mb), "r"(cnt) : "memory");
}

__device__ __forceinline__ void mbar_wait(uint32_t mb, uint32_t parity) {
    asm volatile(
        "{\n\t"
        ".reg .pred P;\n\t"
        "WL_%=: mbarrier.try_wait.parity.acquire.cta.shared::cta.b64 P, [%0], %1, 0x989680;\n\t"
        "@P bra.uni WD_%=;\n\t"
        "bra.uni WL_%=;\n\t"
        "WD_%=:\n\t"
        "}" :: "r"(mb), "r"(parity) : "memory");
}

// one elected thread: expect_tx + 4 bulk-async 20000B copies (one tile)
__device__ __forceinline__ void issue_tile(const float* __restrict__ x,
                                           char* dyn, uint32_t mb,
                                           int buf, long long tile) {
    asm volatile("mbarrier.arrive.expect_tx.shared.b64 _, [%0], %1;"
                 :: "r"(mb), "r"((uint32_t)TILE_BYTES) : "memory");
    const char* src = (const char*)x + (size_t)tile * TILE_BYTES;
    uint32_t dst = s2u(dyn + buf * TILE_BYTES);
    #pragma unroll
    for (int c = 0; c < 4; c++) {
        asm volatile(
            "cp.async.bulk.shared::cta.global.mbarrier::complete_tx::bytes "
            "[%0], [%1], %2, [%3];"
            :: "r"(dst + c * 20000), "l"(src + (size_t)c * 20000),
               "r"(20000u), "r"(mb) : "memory");
    }
}

// ---------------------------------------------------------------- persistent main
// 1 CTA/SM, 1024 threads, double-buffered cp.async.bulk (DRAM fed by
// construction). Per-class accumulators live in 12 registers per thread
// (fixed class<->thread map across tiles); final flush = red.global.add.v4
// into one of 8 replica arrays (380K REDs total, negligible).
__global__ __launch_bounds__(THREADS, 1) void k_main(const float* __restrict__ x,
                                                     float* __restrict__ out,
                                                     int grid) {
    extern __shared__ char dyn[];
    __shared__ float    wred[32];
    __shared__ float    inv[TROWS];
    __shared__ uint64_t mbar[2];

    const int tid = threadIdx.x;
    const int bid = blockIdx.x;
    if (bid == 0 && tid == 0) out[0] = 0.0f;   // ordered before k_fin (stream)

    const uint32_t mb0 = s2u(&mbar[0]);
    const uint32_t mb1 = s2u(&mbar[1]);
    if (tid == 0) { mbar_init(mb0, 1); mbar_init(mb1, 1); }
    __syncthreads();

    const int n = (NTILES - 1 - bid) / grid + 1;   // tiles owned by this CTA
    if (tid == 0) {
        issue_tile(x, dyn, mb0, 0, bid);
        if (n > 1) issue_tile(x, dyn, mb1, 1, bid + (long long)grid);
    }

    float acc[3][4];
    #pragma unroll
    for (int k = 0; k < 3; k++)
        acc[k][0] = acc[k][1] = acc[k][2] = acc[k][3] = 0.0f;

    const int r = tid >> 9;          // 0..1 (512 threads per row)
    const int l = tid & 511;
    int ph0 = 0, ph1 = 0;

    for (int i = 0; i < n; i++) {
        const int buf = i & 1;
        const uint32_t mb = buf ? mb1 : mb0;
        mbar_wait(mb, buf ? ph1 : ph0);
        if (buf) ph1 ^= 1; else ph0 ^= 1;

        // ---- rowsum pass: raw fp32 from SMEM -> exp -> fp16 stage + sum
        const float4* raw4 = reinterpret_cast<const float4*>(dyn + buf * TILE_BYTES) + r * C4;
        uint2*        st   = reinterpret_cast<uint2*>(dyn + STAGE_OFF) + r * C4;

        float s = 0.0f;
        #pragma unroll
        for (int k = 0; k < 5; k++) {
            int j = l + 512 * k;
            if (j < C4) {
                float4 v = raw4[j];
                float e0 = __expf(v.x), e1 = __expf(v.y);
                float e2 = __expf(v.z), e3 = __expf(v.w);
                s += (e0 + e1) + (e2 + e3);
                __half2 h01 = __floats2half2_rn(e0, e1);
                __half2 h23 = __floats2half2_rn(e2, e3);
                st[j] = make_uint2(*reinterpret_cast<unsigned*>(&h01),
                                   *reinterpret_cast<unsigned*>(&h23));
            }
        }
        #pragma unroll
        for (int o = 16; o; o >>= 1) s += __shfl_down_sync(0xffffffffu, s, o);
        if ((tid & 31) == 0) wred[tid >> 5] = s;
        __syncthreads();                       // raw reads + wred/stage writes done

        // re-arm this buffer for tile i+2 while everyone else proceeds
        if (tid == 0 && i + 2 < n)
            issue_tile(x, dyn, mb, buf, bid + (long long)(i + 2) * grid);

        if (tid < TROWS) {
            float t = 0.0f;
            #pragma unroll
            for (int w = 0; w < 16; w++) t += wred[tid * 16 + w];
            inv[tid] = 1.0f / t;
        }
        __syncthreads();
        const float i0 = inv[0], i1 = inv[1];

        // ---- phase B: accumulate fixed classes into registers
        const uint2* st2 = reinterpret_cast<const uint2*>(dyn + STAGE_OFF);
        #pragma unroll
        for (int k = 0; k < 3; k++) {
            int j = tid + 1024 * k;
            if (j < C4) {
                uint2 u0 = st2[j], u1 = st2[C4 + j];
                float2 a = __half22float2(*reinterpret_cast<__half2*>(&u0.x));
                float2 b = __half22float2(*reinterpret_cast<__half2*>(&u0.y));
                float2 c = __half22float2(*reinterpret_cast<__half2*>(&u1.x));
                float2 d = __half22float2(*reinterpret_cast<__half2*>(&u1.y));
                acc[k][0] += a.x * i0 + c.x * i1;
                acc[k][1] += a.y * i0 + c.y * i1;
                acc[k][2] += b.x * i0 + d.x * i1;
                acc[k][3] += b.y * i0 + d.y * i1;
            }
        }
        __syncthreads();   // stage + wred reuse protection for next tile
    }

    // flush: vector-RED into one of 8 replica arrays (16B-aligned rows)
    float* rep = g_rep[bid & (NREP - 1)];
    #pragma unroll
    for (int k = 0; k < 3; k++) {
        int j = tid + 1024 * k;
        if (j < C4) {
            float* p = rep + 4 * j;
            asm volatile("red.global.add.v4.f32 [%0], {%1, %2, %3, %4};"
                         :: "l"(p), "f"(acc[k][0]), "f"(acc[k][1]),
                            "f"(acc[k][2]), "f"(acc[k][3]) : "memory");
        }
    }
}

// ---------------------------------------------------------------- fused epilogue
// 100 blocks x 100 classes: SMEM label histogram from the L2-hot target array,
// sum the 8 replicas (cheap), |conf - count|/B, block-reduce, one atomicAdd —
// then re-zero this block's slice of the replicas for the next graph replay.
__global__ __launch_bounds__(256) void k_fin(const int* __restrict__ tgt,
                                             float* __restrict__ out) {
    __shared__ int   hist[100];
    __shared__ float sm[8];
    const int tid = threadIdx.x;
    const int c0  = blockIdx.x * 100;

    if (tid < 100) hist[tid] = 0;
    __syncthreads();

    // dtype-robust target read: detect int64-LE (odd int32 words zero for
    // values < 2^32) vs int32.
    bool is64 = true;
    #pragma unroll
    for (int j = 1; j < 16; j += 2) is64 = is64 && (tgt[j] == 0);
    for (int i = tid; i < BATCH; i += 256) {
        int t = is64 ? tgt[2 * i] : tgt[i];
        if (t >= c0 && t < c0 + 100) atomicAdd(&hist[t - c0], 1);
    }
    __syncthreads();

    float s = 0.0f;
    if (tid < 100) {
        const int c = c0 + tid;
        float v = 0.0f;
        #pragma unroll
        for (int p = 0; p < NREP; p++) v += g_rep[p][c];
        s = fabsf(v - (float)hist[tid]) * (1.0f / (float)BATCH);
        // consume-then-clear for the next replay (own class columns only)
        #pragma unroll
        for (int p = 0; p < NREP; p++) g_rep[p][c] = 0.0f;
    }

    #pragma unroll
    for (int o = 16; o; o >>= 1) s += __shfl_down_sync(0xffffffffu, s, o);
    if ((tid & 31) == 0) sm[tid >> 5] = s;
    __syncthreads();
    if (tid < 8) {
        float t = sm[tid];
        t += __shfl_down_sync(0xffu, t, 4);
        t += __shfl_down_sync(0xffu, t, 2);
        t += __shfl_down_sync(0xffu, t, 1);
        if (tid == 0) atomicAdd(out, t / (float)CLASSES);
    }
}

// ---------------------------------------------------------------- launch
extern "C" void kernel_launch(void* const* d_in, const int* in_sizes, int n_in,
                              void* d_out, int out_size) {
    const float* x   = (const float*)d_in[0];   // [8192, 10000] fp32
    const int*   tgt = (const int*)d_in[1];     // [8192] int32 or int64 (detected)
    float*       out = (float*)d_out;

    int sms = 0;
    cudaDeviceGetAttribute(&sms, cudaDevAttrMultiProcessorCount, 0);
    int grid = sms;                              // 1 persistent CTA per SM
    if (grid < 1)       grid = 1;
    if (grid > MAXGRID) grid = MAXGRID;

    cudaFuncSetAttribute(k_main, cudaFuncAttributeMaxDynamicSharedMemorySize,
                         SMEM_DYN);

    k_main<<<grid, THREADS, SMEM_DYN>>>(x, out, grid);
    k_fin<<<100, 256>>>(tgt, out);
}